// round 2
// baseline (speedup 1.0000x reference)
#include <cuda_runtime.h>

#define B_DIM 2048
#define T_DIM 32
#define K_DIM 1024
#define D_DIM 256

#define BM 128
#define BN 128
#define BK 16
#define PAD 4

// scratch for per-code squared norms (allocation-free device global)
__device__ float g_csq[T_DIM * K_DIM];

// ---------------------------------------------------------------------------
// Kernel 1: c_sq[t,k] = sum_d codebook[t,k,d]^2.  One warp per code.
// ---------------------------------------------------------------------------
__global__ void csq_kernel(const float* __restrict__ codebook) {
    int gw   = blockIdx.x * (blockDim.x >> 5) + (threadIdx.x >> 5);
    int lane = threadIdx.x & 31;
    if (gw >= T_DIM * K_DIM) return;
    const float4* p = reinterpret_cast<const float4*>(codebook + (size_t)gw * D_DIM);
    float4 v0 = p[lane];
    float4 v1 = p[lane + 32];
    float s = v0.x*v0.x + v0.y*v0.y + v0.z*v0.z + v0.w*v0.w
            + v1.x*v1.x + v1.y*v1.y + v1.z*v1.z + v1.w*v1.w;
    #pragma unroll
    for (int o = 16; o > 0; o >>= 1) s += __shfl_xor_sync(0xffffffffu, s, o);
    if (lane == 0) g_csq[gw] = s;
}

// ---------------------------------------------------------------------------
// Kernel 2: fused  (x . c) GEMM + argmin + codebook gather.
// Block = (one t, one 128-row m-tile). Loops all 8 N-tiles of the K=1024 codes.
// ---------------------------------------------------------------------------
__global__ __launch_bounds__(256, 2) void vsq_kernel(
    const float* __restrict__ input,
    const float* __restrict__ codebook,
    float* __restrict__ out)
{
    __shared__ float As[2][BK][BM + PAD];
    __shared__ float Bs[2][BK][BN + PAD];
    __shared__ float csq_s[K_DIM];
    __shared__ int   sidx[BM];

    const int t     = blockIdx.y;
    const int mBase = blockIdx.x * BM;
    const int tid   = threadIdx.x;
    const int tx    = tid & 15;
    const int ty    = tid >> 4;
    const int tx8   = tx * 8;
    const int ty8   = ty * 8;

    const size_t ARowStride = (size_t)T_DIM * D_DIM;   // stride between consecutive b
    const float* Abase = input    + ((size_t)mBase * T_DIM + t) * D_DIM;
    const float* Cbase = codebook + (size_t)t * K_DIM * D_DIM;

    // stage per-t squared norms into smem
    for (int i = tid; i < K_DIM; i += 256) csq_s[i] = g_csq[t * K_DIM + i];

    // loader mapping: each thread loads 16 contiguous floats/2 float4 of one row
    const int lr = tid >> 1;        // row 0..127
    const int lc = (tid & 1) * 8;   // col offset 0 or 8

    float rmin[8];
    int   ridx[8];
    #pragma unroll
    for (int i = 0; i < 8; i++) { rmin[i] = 3.4e38f; ridx[i] = 0; }

    for (int nTile = 0; nTile < K_DIM / BN; nTile++) {
        const int nBase = nTile * BN;

        float acc[8][8];
        #pragma unroll
        for (int i = 0; i < 8; i++)
            #pragma unroll
            for (int j = 0; j < 8; j++) acc[i][j] = 0.0f;

        const float* Ap = Abase + (size_t)lr * ARowStride + lc;
        const float* Bp = Cbase + (size_t)(nBase + lr) * D_DIM + lc;

        // chunk 0 -> regs -> smem[0]
        float4 ra0 = *reinterpret_cast<const float4*>(Ap);
        float4 ra1 = *reinterpret_cast<const float4*>(Ap + 4);
        float4 rb0 = *reinterpret_cast<const float4*>(Bp);
        float4 rb1 = *reinterpret_cast<const float4*>(Bp + 4);

        int buf = 0;
        As[0][lc + 0][lr] = ra0.x; As[0][lc + 1][lr] = ra0.y;
        As[0][lc + 2][lr] = ra0.z; As[0][lc + 3][lr] = ra0.w;
        As[0][lc + 4][lr] = ra1.x; As[0][lc + 5][lr] = ra1.y;
        As[0][lc + 6][lr] = ra1.z; As[0][lc + 7][lr] = ra1.w;
        Bs[0][lc + 0][lr] = rb0.x; Bs[0][lc + 1][lr] = rb0.y;
        Bs[0][lc + 2][lr] = rb0.z; Bs[0][lc + 3][lr] = rb0.w;
        Bs[0][lc + 4][lr] = rb1.x; Bs[0][lc + 5][lr] = rb1.y;
        Bs[0][lc + 6][lr] = rb1.z; Bs[0][lc + 7][lr] = rb1.w;
        __syncthreads();

        for (int kc = 0; kc < D_DIM / BK; kc++) {
            const bool more = (kc + 1) < (D_DIM / BK);
            if (more) {
                Ap += BK; Bp += BK;
                ra0 = *reinterpret_cast<const float4*>(Ap);
                ra1 = *reinterpret_cast<const float4*>(Ap + 4);
                rb0 = *reinterpret_cast<const float4*>(Bp);
                rb1 = *reinterpret_cast<const float4*>(Bp + 4);
            }

            #pragma unroll
            for (int kk = 0; kk < BK; kk++) {
                float4 a0 = *reinterpret_cast<const float4*>(&As[buf][kk][ty8]);
                float4 a1 = *reinterpret_cast<const float4*>(&As[buf][kk][ty8 + 4]);
                float4 b0 = *reinterpret_cast<const float4*>(&Bs[buf][kk][tx8]);
                float4 b1 = *reinterpret_cast<const float4*>(&Bs[buf][kk][tx8 + 4]);
                float av[8] = {a0.x, a0.y, a0.z, a0.w, a1.x, a1.y, a1.z, a1.w};
                float bv[8] = {b0.x, b0.y, b0.z, b0.w, b1.x, b1.y, b1.z, b1.w};
                #pragma unroll
                for (int i = 0; i < 8; i++)
                    #pragma unroll
                    for (int j = 0; j < 8; j++)
                        acc[i][j] = fmaf(av[i], bv[j], acc[i][j]);
            }
            __syncthreads();

            if (more) {
                const int nb = buf ^ 1;
                As[nb][lc + 0][lr] = ra0.x; As[nb][lc + 1][lr] = ra0.y;
                As[nb][lc + 2][lr] = ra0.z; As[nb][lc + 3][lr] = ra0.w;
                As[nb][lc + 4][lr] = ra1.x; As[nb][lc + 5][lr] = ra1.y;
                As[nb][lc + 6][lr] = ra1.z; As[nb][lc + 7][lr] = ra1.w;
                Bs[nb][lc + 0][lr] = rb0.x; Bs[nb][lc + 1][lr] = rb0.y;
                Bs[nb][lc + 2][lr] = rb0.z; Bs[nb][lc + 3][lr] = rb0.w;
                Bs[nb][lc + 4][lr] = rb1.x; Bs[nb][lc + 5][lr] = rb1.y;
                Bs[nb][lc + 6][lr] = rb1.z; Bs[nb][lc + 7][lr] = rb1.w;
                buf = nb;
                __syncthreads();
            }
        }

        // fold this N-tile into the running argmin.
        // n increases monotonically in the visit order within a thread, so a
        // strict '<' keeps the first occurrence (jnp.argmin semantics).
        #pragma unroll
        for (int j = 0; j < 8; j++) {
            const int n   = nBase + tx8 + j;
            const float cs = csq_s[n];
            #pragma unroll
            for (int i = 0; i < 8; i++) {
                const float d = fmaf(-2.0f, acc[i][j], cs);
                if (d < rmin[i]) { rmin[i] = d; ridx[i] = n; }
            }
        }
    }

    // reduce across the 16 column-threads sharing the same rows.
    // lane = (ty&1)*16 + tx, so xor offsets {8,4,2,1} stay within the tx group.
    #pragma unroll
    for (int i = 0; i < 8; i++) {
        float d  = rmin[i];
        int   ix = ridx[i];
        #pragma unroll
        for (int o = 8; o >= 1; o >>= 1) {
            float od = __shfl_xor_sync(0xffffffffu, d, o);
            int   oi = __shfl_xor_sync(0xffffffffu, ix, o);
            if (od < d || (od == d && oi < ix)) { d = od; ix = oi; }
        }
        if (tx == 0) sidx[ty8 + i] = ix;
    }
    __syncthreads();

    // cooperative gather: embed[b,t,:] = codebook[t, sidx[row], :]
    for (int q = tid; q < BM * (D_DIM / 4); q += 256) {
        const int r = q >> 6;     // row within tile (64 float4 per row)
        const int c = q & 63;
        const int bi = sidx[r];
        float4 v = *reinterpret_cast<const float4*>(Cbase + (size_t)bi * D_DIM + c * 4);
        *reinterpret_cast<float4*>(
            out + ((size_t)(mBase + r) * T_DIM + t) * D_DIM + c * 4) = v;
    }
    // idxes (written as float per the concatenated float32 output)
    if (tid < BM) {
        out[(size_t)B_DIM * T_DIM * D_DIM + (size_t)(mBase + tid) * T_DIM + t]
            = (float)sidx[tid];
    }
}

// ---------------------------------------------------------------------------
extern "C" void kernel_launch(void* const* d_in, const int* in_sizes, int n_in,
                              void* d_out, int out_size) {
    const float* input    = (const float*)d_in[0];
    const float* codebook = (const float*)d_in[1];
    float* out = (float*)d_out;

    // 32768 codes, 8 warps/block
    csq_kernel<<<(T_DIM * K_DIM) / 8, 256>>>(codebook);

    dim3 grid(B_DIM / BM, T_DIM);
    vsq_kernel<<<grid, 256>>>(input, codebook, out);
}

// round 3
// speedup vs baseline: 1.1062x; 1.1062x over previous
#include <cuda_runtime.h>

#define B_DIM 2048
#define T_DIM 32
#define K_DIM 1024
#define D_DIM 256

#define BM 128
#define BN 128
#define BK 16
#define PAD 4

// scratch for per-code squared norms (allocation-free device global)
__device__ float g_csq[T_DIM * K_DIM];

// ---------------------------------------------------------------------------
// Kernel 1: c_sq[t,k] = sum_d codebook[t,k,d]^2.  One warp per code.
// ---------------------------------------------------------------------------
__global__ void csq_kernel(const float* __restrict__ codebook) {
    int gw   = blockIdx.x * (blockDim.x >> 5) + (threadIdx.x >> 5);
    int lane = threadIdx.x & 31;
    if (gw >= T_DIM * K_DIM) return;
    const float4* p = reinterpret_cast<const float4*>(codebook + (size_t)gw * D_DIM);
    float4 v0 = p[lane];
    float4 v1 = p[lane + 32];
    float s = v0.x*v0.x + v0.y*v0.y + v0.z*v0.z + v0.w*v0.w
            + v1.x*v1.x + v1.y*v1.y + v1.z*v1.z + v1.w*v1.w;
    #pragma unroll
    for (int o = 16; o > 0; o >>= 1) s += __shfl_xor_sync(0xffffffffu, s, o);
    if (lane == 0) g_csq[gw] = s;
}

// ---------------------------------------------------------------------------
// Kernel 2: fused (x . c) GEMM + argmin + codebook gather.
// Block = (one t, one 128-row m-tile). Loops all 8 N-tiles of the K=1024 codes.
// Thread tile: 8x8 as 2x2 quads of 4x4 — rows {ty*4, 64+ty*4}, cols
// {tx*4, 64+tx*4} — so fragment LDS.128s are 16B-stride conflict-free.
// ---------------------------------------------------------------------------
__global__ __launch_bounds__(256, 2) void vsq_kernel(
    const float* __restrict__ input,
    const float* __restrict__ codebook,
    float* __restrict__ out)
{
    __shared__ float As[2][BK][BM + PAD];
    __shared__ float Bs[2][BK][BN + PAD];
    __shared__ float csq_s[K_DIM];
    __shared__ int   sidx[BM];

    const int t     = blockIdx.y;
    const int mBase = blockIdx.x * BM;
    const int tid   = threadIdx.x;
    const int tx    = tid & 15;
    const int ty    = tid >> 4;
    const int txc   = tx * 4;      // col base within half-tile
    const int tyc   = ty * 4;      // row base within half-tile

    const size_t ARowStride = (size_t)T_DIM * D_DIM;   // stride between consecutive b
    const float* Abase = input    + ((size_t)mBase * T_DIM + t) * D_DIM;
    const float* Cbase = codebook + (size_t)t * K_DIM * D_DIM;

    // stage per-t squared norms into smem
    for (int i = tid; i < K_DIM; i += 256) csq_s[i] = g_csq[t * K_DIM + i];

    // loader mapping: each thread loads 16 contiguous floats/2 float4 of one row
    const int lr = tid >> 1;        // row 0..127
    const int lc = (tid & 1) * 8;   // col offset 0 or 8

    float rmin[8];
    int   ridx[8];
    #pragma unroll
    for (int i = 0; i < 8; i++) { rmin[i] = 3.4e38f; ridx[i] = 0; }

    for (int nTile = 0; nTile < K_DIM / BN; nTile++) {
        const int nBase = nTile * BN;

        float acc[8][8];
        #pragma unroll
        for (int i = 0; i < 8; i++)
            #pragma unroll
            for (int j = 0; j < 8; j++) acc[i][j] = 0.0f;

        const float* Ap = Abase + (size_t)lr * ARowStride + lc;
        const float* Bp = Cbase + (size_t)(nBase + lr) * D_DIM + lc;

        // chunk 0 -> regs -> smem[0]
        float4 ra0 = *reinterpret_cast<const float4*>(Ap);
        float4 ra1 = *reinterpret_cast<const float4*>(Ap + 4);
        float4 rb0 = *reinterpret_cast<const float4*>(Bp);
        float4 rb1 = *reinterpret_cast<const float4*>(Bp + 4);

        int buf = 0;
        As[0][lc + 0][lr] = ra0.x; As[0][lc + 1][lr] = ra0.y;
        As[0][lc + 2][lr] = ra0.z; As[0][lc + 3][lr] = ra0.w;
        As[0][lc + 4][lr] = ra1.x; As[0][lc + 5][lr] = ra1.y;
        As[0][lc + 6][lr] = ra1.z; As[0][lc + 7][lr] = ra1.w;
        Bs[0][lc + 0][lr] = rb0.x; Bs[0][lc + 1][lr] = rb0.y;
        Bs[0][lc + 2][lr] = rb0.z; Bs[0][lc + 3][lr] = rb0.w;
        Bs[0][lc + 4][lr] = rb1.x; Bs[0][lc + 5][lr] = rb1.y;
        Bs[0][lc + 6][lr] = rb1.z; Bs[0][lc + 7][lr] = rb1.w;
        __syncthreads();

        for (int kc = 0; kc < D_DIM / BK; kc++) {
            const bool more = (kc + 1) < (D_DIM / BK);
            if (more) {
                Ap += BK; Bp += BK;
                ra0 = *reinterpret_cast<const float4*>(Ap);
                ra1 = *reinterpret_cast<const float4*>(Ap + 4);
                rb0 = *reinterpret_cast<const float4*>(Bp);
                rb1 = *reinterpret_cast<const float4*>(Bp + 4);
            }

            #pragma unroll
            for (int kk = 0; kk < BK; kk++) {
                float4 a0 = *reinterpret_cast<const float4*>(&As[buf][kk][tyc]);
                float4 a1 = *reinterpret_cast<const float4*>(&As[buf][kk][tyc + 64]);
                float4 b0 = *reinterpret_cast<const float4*>(&Bs[buf][kk][txc]);
                float4 b1 = *reinterpret_cast<const float4*>(&Bs[buf][kk][txc + 64]);
                float av[8] = {a0.x, a0.y, a0.z, a0.w, a1.x, a1.y, a1.z, a1.w};
                float bv[8] = {b0.x, b0.y, b0.z, b0.w, b1.x, b1.y, b1.z, b1.w};
                #pragma unroll
                for (int i = 0; i < 8; i++)
                    #pragma unroll
                    for (int j = 0; j < 8; j++)
                        acc[i][j] = fmaf(av[i], bv[j], acc[i][j]);
            }

            // single sync per step: stores target buf^1, whose last readers
            // were ordered by the previous iteration's barrier.
            if (more) {
                const int nb = buf ^ 1;
                As[nb][lc + 0][lr] = ra0.x; As[nb][lc + 1][lr] = ra0.y;
                As[nb][lc + 2][lr] = ra0.z; As[nb][lc + 3][lr] = ra0.w;
                As[nb][lc + 4][lr] = ra1.x; As[nb][lc + 5][lr] = ra1.y;
                As[nb][lc + 6][lr] = ra1.z; As[nb][lc + 7][lr] = ra1.w;
                Bs[nb][lc + 0][lr] = rb0.x; Bs[nb][lc + 1][lr] = rb0.y;
                Bs[nb][lc + 2][lr] = rb0.z; Bs[nb][lc + 3][lr] = rb0.w;
                Bs[nb][lc + 4][lr] = rb1.x; Bs[nb][lc + 5][lr] = rb1.y;
                Bs[nb][lc + 6][lr] = rb1.z; Bs[nb][lc + 7][lr] = rb1.w;
                buf = nb;
            }
            __syncthreads();
        }

        // fold this N-tile into the running argmin.
        // n increases monotonically in the visit order within a thread, so a
        // strict '<' keeps the first occurrence (jnp.argmin semantics).
        #pragma unroll
        for (int jh = 0; jh < 2; jh++) {
            #pragma unroll
            for (int jj = 0; jj < 4; jj++) {
                const int j = jh * 4 + jj;
                const int n = nBase + jh * 64 + txc + jj;
                const float cs = csq_s[n];
                #pragma unroll
                for (int i = 0; i < 8; i++) {
                    const float d = fmaf(-2.0f, acc[i][j], cs);
                    if (d < rmin[i]) { rmin[i] = d; ridx[i] = n; }
                }
            }
        }
    }

    // reduce across the 16 column-threads sharing the same rows.
    // lane = (ty&1)*16 + tx, so xor offsets {8,4,2,1} stay within the tx group.
    #pragma unroll
    for (int i = 0; i < 8; i++) {
        float d  = rmin[i];
        int   ix = ridx[i];
        #pragma unroll
        for (int o = 8; o >= 1; o >>= 1) {
            float od = __shfl_xor_sync(0xffffffffu, d, o);
            int   oi = __shfl_xor_sync(0xffffffffu, ix, o);
            if (od < d || (od == d && oi < ix)) { d = od; ix = oi; }
        }
        if (tx == 0) {
            const int r = (i < 4) ? (tyc + i) : (64 + tyc + i - 4);
            sidx[r] = ix;
        }
    }
    __syncthreads();

    // cooperative gather: embed[b,t,:] = codebook[t, sidx[row], :]
    for (int q = tid; q < BM * (D_DIM / 4); q += 256) {
        const int r = q >> 6;     // row within tile (64 float4 per row)
        const int c = q & 63;
        const int bi = sidx[r];
        float4 v = *reinterpret_cast<const float4*>(Cbase + (size_t)bi * D_DIM + c * 4);
        *reinterpret_cast<float4*>(
            out + ((size_t)(mBase + r) * T_DIM + t) * D_DIM + c * 4) = v;
    }
    // idxes (written as float per the concatenated float32 output)
    if (tid < BM) {
        out[(size_t)B_DIM * T_DIM * D_DIM + (size_t)(mBase + tid) * T_DIM + t]
            = (float)sidx[tid];
    }
}

// ---------------------------------------------------------------------------
extern "C" void kernel_launch(void* const* d_in, const int* in_sizes, int n_in,
                              void* d_out, int out_size) {
    const float* input    = (const float*)d_in[0];
    const float* codebook = (const float*)d_in[1];
    float* out = (float*)d_out;

    // 32768 codes, 8 warps/block
    csq_kernel<<<(T_DIM * K_DIM) / 8, 256>>>(codebook);

    dim3 grid(B_DIM / BM, T_DIM);
    vsq_kernel<<<grid, 256>>>(input, codebook, out);
}

// round 4
// speedup vs baseline: 1.2311x; 1.1129x over previous
#include <cuda_runtime.h>

#define B_DIM 2048
#define T_DIM 32
#define K_DIM 1024
#define D_DIM 256

#define BM 128
#define BN 128
#define BK 16
#define PAD 4

// scratch for per-code squared norms (allocation-free device global)
__device__ float g_csq[T_DIM * K_DIM];

// ---------------------------------------------------------------------------
// Kernel 1: c_sq[t,k] = sum_d codebook[t,k,d]^2.  One warp per code.
// ---------------------------------------------------------------------------
__global__ void csq_kernel(const float* __restrict__ codebook) {
    int gw   = blockIdx.x * (blockDim.x >> 5) + (threadIdx.x >> 5);
    int lane = threadIdx.x & 31;
    if (gw >= T_DIM * K_DIM) return;
    const float4* p = reinterpret_cast<const float4*>(codebook + (size_t)gw * D_DIM);
    float4 v0 = p[lane];
    float4 v1 = p[lane + 32];
    float s = v0.x*v0.x + v0.y*v0.y + v0.z*v0.z + v0.w*v0.w
            + v1.x*v1.x + v1.y*v1.y + v1.z*v1.z + v1.w*v1.w;
    #pragma unroll
    for (int o = 16; o > 0; o >>= 1) s += __shfl_xor_sync(0xffffffffu, s, o);
    if (lane == 0) g_csq[gw] = s;
}

// packed f32x2 helpers (Blackwell FFMA2 — only reachable via PTX)
#define FMA_F32X2(d, a, b) \
    asm("fma.rn.f32x2 %0, %1, %2, %0;" : "+l"(d) : "l"(a), "l"(b))
#define DUP_F32X2(d, s) \
    asm("mov.b64 %0, {%1, %1};" : "=l"(d) : "f"(s))
#define UNPK_F32X2(lo, hi, s) \
    asm("mov.b64 {%0, %1}, %2;" : "=f"(lo), "=f"(hi) : "l"(s))

// ---------------------------------------------------------------------------
// Kernel 2: fused (x . c) GEMM + argmin + codebook gather.
// Block = (one t, one 128-row m-tile). Loops all 8 N-tiles of the K=1024 codes.
// Thread tile: 8 rows x 8 cols as 2x2 quads of 4x4 — rows {ty*4, 64+ty*4},
// cols {tx*4, 64+tx*4}. Accumulators packed pairwise along cols as f32x2;
// inner product uses fma.rn.f32x2 (FFMA2) = 2 MACs per issued instruction.
// ---------------------------------------------------------------------------
__global__ __launch_bounds__(256, 2) void vsq_kernel(
    const float* __restrict__ input,
    const float* __restrict__ codebook,
    float* __restrict__ out)
{
    __shared__ float As[2][BK][BM + PAD];
    __shared__ float Bs[2][BK][BN + PAD];
    __shared__ float csq_s[K_DIM];
    __shared__ int   sidx[BM];

    const int t     = blockIdx.y;
    const int mBase = blockIdx.x * BM;
    const int tid   = threadIdx.x;
    const int tx    = tid & 15;
    const int ty    = tid >> 4;
    const int txc   = tx * 4;      // col base within half-tile
    const int tyc   = ty * 4;      // row base within half-tile

    const size_t ARowStride = (size_t)T_DIM * D_DIM;   // stride between consecutive b
    const float* Abase = input    + ((size_t)mBase * T_DIM + t) * D_DIM;
    const float* Cbase = codebook + (size_t)t * K_DIM * D_DIM;

    // stage per-t squared norms into smem
    for (int i = tid; i < K_DIM; i += 256) csq_s[i] = g_csq[t * K_DIM + i];

    // loader mapping: each thread loads 16 contiguous floats/2 float4 of one row
    const int lr = tid >> 1;        // row 0..127
    const int lc = (tid & 1) * 8;   // col offset 0 or 8

    float rmin[8];
    int   ridx[8];
    #pragma unroll
    for (int i = 0; i < 8; i++) { rmin[i] = 3.4e38f; ridx[i] = 0; }

    for (int nTile = 0; nTile < K_DIM / BN; nTile++) {
        const int nBase = nTile * BN;

        // packed accumulators: acc2[i][jp] = {col 2jp, col 2jp+1} of row i
        unsigned long long acc2[8][4];
        #pragma unroll
        for (int i = 0; i < 8; i++)
            #pragma unroll
            for (int jp = 0; jp < 4; jp++) acc2[i][jp] = 0ull;

        const float* Ap = Abase + (size_t)lr * ARowStride + lc;
        const float* Bp = Cbase + (size_t)(nBase + lr) * D_DIM + lc;

        // chunk 0 -> regs -> smem[0]
        float4 ra0 = *reinterpret_cast<const float4*>(Ap);
        float4 ra1 = *reinterpret_cast<const float4*>(Ap + 4);
        float4 rb0 = *reinterpret_cast<const float4*>(Bp);
        float4 rb1 = *reinterpret_cast<const float4*>(Bp + 4);

        int buf = 0;
        As[0][lc + 0][lr] = ra0.x; As[0][lc + 1][lr] = ra0.y;
        As[0][lc + 2][lr] = ra0.z; As[0][lc + 3][lr] = ra0.w;
        As[0][lc + 4][lr] = ra1.x; As[0][lc + 5][lr] = ra1.y;
        As[0][lc + 6][lr] = ra1.z; As[0][lc + 7][lr] = ra1.w;
        Bs[0][lc + 0][lr] = rb0.x; Bs[0][lc + 1][lr] = rb0.y;
        Bs[0][lc + 2][lr] = rb0.z; Bs[0][lc + 3][lr] = rb0.w;
        Bs[0][lc + 4][lr] = rb1.x; Bs[0][lc + 5][lr] = rb1.y;
        Bs[0][lc + 6][lr] = rb1.z; Bs[0][lc + 7][lr] = rb1.w;
        __syncthreads();

        for (int kc = 0; kc < D_DIM / BK; kc++) {
            const bool more = (kc + 1) < (D_DIM / BK);
            if (more) {
                Ap += BK; Bp += BK;
                ra0 = *reinterpret_cast<const float4*>(Ap);
                ra1 = *reinterpret_cast<const float4*>(Ap + 4);
                rb0 = *reinterpret_cast<const float4*>(Bp);
                rb1 = *reinterpret_cast<const float4*>(Bp + 4);
            }

            #pragma unroll
            for (int kk = 0; kk < BK; kk++) {
                float4 a0 = *reinterpret_cast<const float4*>(&As[buf][kk][tyc]);
                float4 a1 = *reinterpret_cast<const float4*>(&As[buf][kk][tyc + 64]);
                // B fragments as aligned 64-bit packed pairs (16B-aligned:
                // row stride (BM+PAD)*4 = 528B and txc*4 are 16B multiples)
                ulonglong2 bq0 = *reinterpret_cast<const ulonglong2*>(&Bs[buf][kk][txc]);
                ulonglong2 bq1 = *reinterpret_cast<const ulonglong2*>(&Bs[buf][kk][txc + 64]);
                unsigned long long bbv[4] = {bq0.x, bq0.y, bq1.x, bq1.y};
                float av[8] = {a0.x, a0.y, a0.z, a0.w, a1.x, a1.y, a1.z, a1.w};
                #pragma unroll
                for (int i = 0; i < 8; i++) {
                    unsigned long long aa;
                    DUP_F32X2(aa, av[i]);
                    #pragma unroll
                    for (int jp = 0; jp < 4; jp++)
                        FMA_F32X2(acc2[i][jp], aa, bbv[jp]);
                }
            }

            // single sync per step: stores target buf^1, whose last readers
            // were ordered by the previous iteration's barrier.
            if (more) {
                const int nb = buf ^ 1;
                As[nb][lc + 0][lr] = ra0.x; As[nb][lc + 1][lr] = ra0.y;
                As[nb][lc + 2][lr] = ra0.z; As[nb][lc + 3][lr] = ra0.w;
                As[nb][lc + 4][lr] = ra1.x; As[nb][lc + 5][lr] = ra1.y;
                As[nb][lc + 6][lr] = ra1.z; As[nb][lc + 7][lr] = ra1.w;
                Bs[nb][lc + 0][lr] = rb0.x; Bs[nb][lc + 1][lr] = rb0.y;
                Bs[nb][lc + 2][lr] = rb0.z; Bs[nb][lc + 3][lr] = rb0.w;
                Bs[nb][lc + 4][lr] = rb1.x; Bs[nb][lc + 5][lr] = rb1.y;
                Bs[nb][lc + 6][lr] = rb1.z; Bs[nb][lc + 7][lr] = rb1.w;
                buf = nb;
            }
            __syncthreads();
        }

        // fold this N-tile into the running argmin.
        // jp 0..3 -> cols {txc, txc+1}, {txc+2, txc+3}, {64+txc, 64+txc+1},
        // {64+txc+2, 64+txc+3}: strictly increasing n per thread, so '<'
        // keeps the first occurrence (jnp.argmin semantics).
        #pragma unroll
        for (int jp = 0; jp < 4; jp++) {
            const int nb0 = nBase + ((jp >> 1) ? 64 : 0) + txc + (jp & 1) * 2;
            const float cs0 = csq_s[nb0];
            const float cs1 = csq_s[nb0 + 1];
            #pragma unroll
            for (int i = 0; i < 8; i++) {
                float xc0, xc1;
                UNPK_F32X2(xc0, xc1, acc2[i][jp]);
                const float d0 = fmaf(-2.0f, xc0, cs0);
                const float d1 = fmaf(-2.0f, xc1, cs1);
                if (d0 < rmin[i]) { rmin[i] = d0; ridx[i] = nb0; }
                if (d1 < rmin[i]) { rmin[i] = d1; ridx[i] = nb0 + 1; }
            }
        }
    }

    // reduce across the 16 column-threads sharing the same rows.
    // lane = (ty&1)*16 + tx, so xor offsets {8,4,2,1} stay within the tx group.
    #pragma unroll
    for (int i = 0; i < 8; i++) {
        float d  = rmin[i];
        int   ix = ridx[i];
        #pragma unroll
        for (int o = 8; o >= 1; o >>= 1) {
            float od = __shfl_xor_sync(0xffffffffu, d, o);
            int   oi = __shfl_xor_sync(0xffffffffu, ix, o);
            if (od < d || (od == d && oi < ix)) { d = od; ix = oi; }
        }
        if (tx == 0) {
            const int r = (i < 4) ? (tyc + i) : (64 + tyc + i - 4);
            sidx[r] = ix;
        }
    }
    __syncthreads();

    // cooperative gather: embed[b,t,:] = codebook[t, sidx[row], :]
    for (int q = tid; q < BM * (D_DIM / 4); q += 256) {
        const int r = q >> 6;     // row within tile (64 float4 per row)
        const int c = q & 63;
        const int bi = sidx[r];
        float4 v = *reinterpret_cast<const float4*>(Cbase + (size_t)bi * D_DIM + c * 4);
        *reinterpret_cast<float4*>(
            out + ((size_t)(mBase + r) * T_DIM + t) * D_DIM + c * 4) = v;
    }
    // idxes (written as float per the concatenated float32 output)
    if (tid < BM) {
        out[(size_t)B_DIM * T_DIM * D_DIM + (size_t)(mBase + tid) * T_DIM + t]
            = (float)sidx[tid];
    }
}

// ---------------------------------------------------------------------------
extern "C" void kernel_launch(void* const* d_in, const int* in_sizes, int n_in,
                              void* d_out, int out_size) {
    const float* input    = (const float*)d_in[0];
    const float* codebook = (const float*)d_in[1];
    float* out = (float*)d_out;

    // 32768 codes, 8 warps/block
    csq_kernel<<<(T_DIM * K_DIM) / 8, 256>>>(codebook);

    dim3 grid(B_DIM / BM, T_DIM);
    vsq_kernel<<<grid, 256>>>(input, codebook, out);
}

// round 7
// speedup vs baseline: 1.3134x; 1.0669x over previous
#include <cuda_runtime.h>
#include <cstdint>

#define B_DIM 2048
#define T_DIM 32
#define K_DIM 1024
#define D_DIM 256

#define BM 128
#define BN 128
#define BK 32
#define SROW 132            // BM + 4 pad (floats per k-row in smem)

__device__ float g_csq[T_DIM * K_DIM];

// ---------------------------------------------------------------------------
// Kernel 1: c_sq[t,k] = sum_d codebook[t,k,d]^2.  One warp per code.
// ---------------------------------------------------------------------------
__global__ void csq_kernel(const float* __restrict__ codebook) {
    int gw   = blockIdx.x * (blockDim.x >> 5) + (threadIdx.x >> 5);
    int lane = threadIdx.x & 31;
    if (gw >= T_DIM * K_DIM) return;
    const float4* p = reinterpret_cast<const float4*>(codebook + (size_t)gw * D_DIM);
    float4 v0 = p[lane];
    float4 v1 = p[lane + 32];
    float s = v0.x*v0.x + v0.y*v0.y + v0.z*v0.z + v0.w*v0.w
            + v1.x*v1.x + v1.y*v1.y + v1.z*v1.z + v1.w*v1.w;
    #pragma unroll
    for (int o = 16; o > 0; o >>= 1) s += __shfl_xor_sync(0xffffffffu, s, o);
    if (lane == 0) g_csq[gw] = s;
}

// m16n8k8 TF32 warp MMA (sm_80+ PTX — valid on base sm_100 target)
__device__ __forceinline__ void mma_tf32(float* c, const uint32_t* a,
                                         const uint32_t* b) {
    asm volatile(
        "mma.sync.aligned.m16n8k8.row.col.f32.tf32.tf32.f32 "
        "{%0,%1,%2,%3}, {%4,%5,%6,%7}, {%8,%9}, {%0,%1,%2,%3};"
        : "+f"(c[0]), "+f"(c[1]), "+f"(c[2]), "+f"(c[3])
        : "r"(a[0]), "r"(a[1]), "r"(a[2]), "r"(a[3]), "r"(b[0]), "r"(b[1]));
}

// ---------------------------------------------------------------------------
// Kernel 2: fused GEMM (3xTF32 split via mma.sync) + argmin + gather.
// CTA = 256 thr (8 warps, 2x4), one t, 128 input rows; loops 8 N-tiles.
// smem K-major [k][m+pad] double-buffered, BK=32.
// ---------------------------------------------------------------------------
__global__ __launch_bounds__(256, 2) void vsq_mma_kernel(
    const float* __restrict__ input,
    const float* __restrict__ codebook,
    float* __restrict__ out)
{
    extern __shared__ float sm[];
    float* csq_s = sm;                                        // 1024 floats
    unsigned long long* minpack =
        reinterpret_cast<unsigned long long*>(sm + 1024);     // 128 ull
    float* bufs = sm + 1280;                                  // 2 x 8448 floats

    const int t     = blockIdx.y;
    const int mBase = blockIdx.x * BM;
    const int tid   = threadIdx.x;
    const int lane  = tid & 31;
    const int wid   = tid >> 5;
    const int wm    = wid >> 2;        // 0..1  (m half)
    const int wn    = wid & 3;         // 0..3  (n quarter)
    const int lq    = lane >> 2;       // 0..7
    const int lr4   = lane & 3;        // 0..3

    // loader mapping: one row, 16 contiguous k per thread
    const int lr = tid >> 1;
    const int lc = (tid & 1) * 16;

    for (int i = tid; i < K_DIM; i += 256) csq_s[i] = g_csq[t * K_DIM + i];
    if (tid < BM) minpack[tid] = 0xFFFFFFFFFFFFFFFFull;
    __syncthreads();

    const size_t ARowStride = (size_t)T_DIM * D_DIM;
    const float* Abase = input    + ((size_t)mBase * T_DIM + t) * D_DIM;
    const float* Cb    = codebook + (size_t)t * K_DIM * D_DIM;

    float rmin[8];
    int   ridx[8];
    #pragma unroll
    for (int i = 0; i < 8; i++) { rmin[i] = 3.4e38f; ridx[i] = 0; }

    int buf = 0;
    for (int nTile = 0; nTile < K_DIM / BN; nTile++) {
        const int nBase = nTile * BN;

        float acc[4][4][4];
        #pragma unroll
        for (int mf = 0; mf < 4; mf++)
            #pragma unroll
            for (int nf = 0; nf < 4; nf++)
                #pragma unroll
                for (int r = 0; r < 4; r++) acc[mf][nf][r] = 0.0f;

        const float* Ap = Abase + (size_t)lr * ARowStride + lc;
        const float* Bp = Cb + (size_t)(nBase + lr) * D_DIM + lc;

        float va[16], vb[16];
        #pragma unroll
        for (int i = 0; i < 4; i++) {
            *reinterpret_cast<float4*>(va + i * 4) =
                *reinterpret_cast<const float4*>(Ap + i * 4);
            *reinterpret_cast<float4*>(vb + i * 4) =
                *reinterpret_cast<const float4*>(Bp + i * 4);
        }
        {
            float* As = bufs + buf * 8448;
            float* Bs = As + 4224;
            #pragma unroll
            for (int e = 0; e < 16; e++) {
                As[(lc + e) * SROW + lr] = va[e];
                Bs[(lc + e) * SROW + lr] = vb[e];
            }
        }
        __syncthreads();

        for (int kt = 0; kt < D_DIM / BK; kt++) {
            const bool more = (kt + 1) < (D_DIM / BK);
            if (more) {
                Ap += BK; Bp += BK;
                #pragma unroll
                for (int i = 0; i < 4; i++) {
                    *reinterpret_cast<float4*>(va + i * 4) =
                        *reinterpret_cast<const float4*>(Ap + i * 4);
                    *reinterpret_cast<float4*>(vb + i * 4) =
                        *reinterpret_cast<const float4*>(Bp + i * 4);
                }
            }

            const float* As = bufs + buf * 8448;
            const float* Bs = As + 4224;

            #pragma unroll
            for (int kf = 0; kf < 4; kf++) {
                // B fragments for all 4 n-frags, split hi/lo
                uint32_t bh[4][2], bl[4][2];
                #pragma unroll
                for (int nf = 0; nf < 4; nf++)
                    #pragma unroll
                    for (int j = 0; j < 2; j++) {
                        float v = Bs[(kf * 8 + lr4 + j * 4) * SROW
                                     + wn * 32 + nf * 8 + lq];
                        uint32_t hb = __float_as_uint(v) & 0xFFFFE000u;
                        bh[nf][j] = hb;
                        bl[nf][j] = __float_as_uint(v - __uint_as_float(hb));
                    }
                #pragma unroll
                for (int mf = 0; mf < 4; mf++) {
                    uint32_t ah[4], al[4];
                    #pragma unroll
                    for (int j = 0; j < 4; j++) {
                        float v = As[(kf * 8 + lr4 + (j >> 1) * 4) * SROW
                                     + wm * 64 + mf * 16 + lq + (j & 1) * 8];
                        uint32_t hb = __float_as_uint(v) & 0xFFFFE000u;
                        ah[j] = hb;
                        al[j] = __float_as_uint(v - __uint_as_float(hb));
                    }
                    #pragma unroll
                    for (int nf = 0; nf < 4; nf++) {
                        mma_tf32(acc[mf][nf], al, bh[nf]);  // small terms first
                        mma_tf32(acc[mf][nf], ah, bl[nf]);
                        mma_tf32(acc[mf][nf], ah, bh[nf]);
                    }
                }
            }

            if (more) {
                const int nb = buf ^ 1;
                float* Asn = bufs + nb * 8448;
                float* Bsn = Asn + 4224;
                #pragma unroll
                for (int e = 0; e < 16; e++) {
                    Asn[(lc + e) * SROW + lr] = va[e];
                    Bsn[(lc + e) * SROW + lr] = vb[e];
                }
                buf = nb;
            }
            __syncthreads();
        }

        // fold into running argmin (per-thread n strictly ascending ->
        // '<' keeps first occurrence, matching jnp.argmin)
        #pragma unroll
        for (int mf = 0; mf < 4; mf++)
            #pragma unroll
            for (int half = 0; half < 2; half++) {
                const int i = mf * 2 + half;
                #pragma unroll
                for (int nf = 0; nf < 4; nf++) {
                    const int n0 = nBase + wn * 32 + nf * 8 + lr4 * 2;
                    const float d0 = fmaf(-2.0f, acc[mf][nf][half * 2 + 0], csq_s[n0]);
                    const float d1 = fmaf(-2.0f, acc[mf][nf][half * 2 + 1], csq_s[n0 + 1]);
                    if (d0 < rmin[i]) { rmin[i] = d0; ridx[i] = n0; }
                    if (d1 < rmin[i]) { rmin[i] = d1; ridx[i] = n0 + 1; }
                }
            }
    }

    // reduce across the 4 lanes sharing each row (xor 1,2 within quad),
    // then global combine across the 4 n-warps via packed atomicMin.
    #pragma unroll
    for (int i = 0; i < 8; i++) {
        float d  = rmin[i];
        int   ix = ridx[i];
        #pragma unroll
        for (int o = 1; o <= 2; o <<= 1) {
            float od = __shfl_xor_sync(0xffffffffu, d, o);
            int   oi = __shfl_xor_sync(0xffffffffu, ix, o);
            if (od < d || (od == d && oi < ix)) { d = od; ix = oi; }
        }
        if (lr4 == 0) {
            const int row = wm * 64 + (i >> 1) * 16 + (i & 1) * 8 + lq;
            uint32_t db = __float_as_uint(d);
            uint32_t key = (db & 0x80000000u) ? ~db : (db | 0x80000000u);
            unsigned long long pk =
                ((unsigned long long)key << 32) | (uint32_t)ix;
            atomicMin(&minpack[row], pk);
        }
    }
    __syncthreads();

    // cooperative gather: embed[b,t,:] = codebook[t, argmin, :]
    for (int q = tid; q < BM * (D_DIM / 4); q += 256) {
        const int r  = q >> 6;
        const int c  = q & 63;
        const int bi = (int)(uint32_t)(minpack[r] & 0xFFFFFFFFull);
        float4 v = *reinterpret_cast<const float4*>(Cb + (size_t)bi * D_DIM + c * 4);
        *reinterpret_cast<float4*>(
            out + ((size_t)(mBase + r) * T_DIM + t) * D_DIM + c * 4) = v;
    }
    // idxes (float, concatenated after embed in the float32 output)
    if (tid < BM) {
        out[(size_t)B_DIM * T_DIM * D_DIM + (size_t)(mBase + tid) * T_DIM + t]
            = (float)(uint32_t)(minpack[tid] & 0xFFFFFFFFull);
    }
}

// ---------------------------------------------------------------------------
static const uint32_t SMEM_BYTES = (1280u + 2u * 8448u) * 4u;  // 72704

extern "C" void kernel_launch(void* const* d_in, const int* in_sizes, int n_in,
                              void* d_out, int out_size) {
    const float* input    = (const float*)d_in[0];
    const float* codebook = (const float*)d_in[1];
    float* out = (float*)d_out;

    cudaFuncSetAttribute(vsq_mma_kernel,
                         cudaFuncAttributeMaxDynamicSharedMemorySize, SMEM_BYTES);

    csq_kernel<<<(T_DIM * K_DIM) / 8, 256>>>(codebook);

    dim3 grid(B_DIM / BM, T_DIM);
    vsq_mma_kernel<<<grid, 256, SMEM_BYTES>>>(input, codebook, out);
}

// round 10
// speedup vs baseline: 1.5173x; 1.1552x over previous
#include <cuda_runtime.h>
#include <cstdint>

#define B_DIM 2048
#define T_DIM 32
#define K_DIM 1024
#define D_DIM 256

#define BM 128
#define BN 128
#define BK 16

// smem addressing for split tiles: [k][row], row stride 136 (==8 mod 32 ->
// fragment LDS banks 8*lr4+lq all-distinct), plus 16-float offset for k>=8 so
// the two k-halves written by one STS instruction hit disjoint bank groups.
#define KADDR(k, row) ((k) * 136 + (((k) >> 3) & 1) * 16 + (row))
#define ARR_STRIDE 2192            // > KADDR(15,135)=2191, 16B-aligned*4

__device__ float g_csq[T_DIM * K_DIM];

// ---------------------------------------------------------------------------
// Kernel 1: c_sq[t,k] = sum_d codebook[t,k,d]^2.  One warp per code.
// ---------------------------------------------------------------------------
__global__ void csq_kernel(const float* __restrict__ codebook) {
    int gw   = blockIdx.x * (blockDim.x >> 5) + (threadIdx.x >> 5);
    int lane = threadIdx.x & 31;
    if (gw >= T_DIM * K_DIM) return;
    const float4* p = reinterpret_cast<const float4*>(codebook + (size_t)gw * D_DIM);
    float4 v0 = p[lane];
    float4 v1 = p[lane + 32];
    float s = v0.x*v0.x + v0.y*v0.y + v0.z*v0.z + v0.w*v0.w
            + v1.x*v1.x + v1.y*v1.y + v1.z*v1.z + v1.w*v1.w;
    #pragma unroll
    for (int o = 16; o > 0; o >>= 1) s += __shfl_xor_sync(0xffffffffu, s, o);
    if (lane == 0) g_csq[gw] = s;
}

// m16n8k8 TF32 warp MMA (sm_80+ PTX — valid on base sm_100 target)
__device__ __forceinline__ void mma_tf32(float* c, const uint32_t* a,
                                         const uint32_t* b) {
    asm volatile(
        "mma.sync.aligned.m16n8k8.row.col.f32.tf32.tf32.f32 "
        "{%0,%1,%2,%3}, {%4,%5,%6,%7}, {%8,%9}, {%0,%1,%2,%3};"
        : "+f"(c[0]), "+f"(c[1]), "+f"(c[2]), "+f"(c[3])
        : "r"(a[0]), "r"(a[1]), "r"(a[2]), "r"(a[3]), "r"(b[0]), "r"(b[1]));
}

// ---------------------------------------------------------------------------
// Kernel 2: fused GEMM (3xTF32 split via mma.sync) + argmin + gather.
// CTA = 256 thr (8 warps, 2x4), one t, 128 input rows; loops 8 N-tiles.
// Hi/lo tf32 split done ONCE at staging; smem holds Ah/Al/Bh/Bl (BK=16,
// double-buffered); inner loop is pure conflict-free LDS + HMMA.
// ---------------------------------------------------------------------------
__global__ __launch_bounds__(256, 2) void vsq_mma_kernel(
    const float* __restrict__ input,
    const float* __restrict__ codebook,
    float* __restrict__ out)
{
    extern __shared__ float sm[];
    float* csq_s = sm;                                        // 1024 floats
    unsigned long long* minpack =
        reinterpret_cast<unsigned long long*>(sm + 1024);     // 128 ull
    float* bufs = sm + 1280;                                  // 2 x 4 x ARR_STRIDE

    const int t     = blockIdx.y;
    const int mBase = blockIdx.x * BM;
    const int tid   = threadIdx.x;
    const int lane  = tid & 31;
    const int wid   = tid >> 5;
    const int wm    = wid >> 2;        // 0..1  (m half)
    const int wn    = wid & 3;         // 0..3  (n quarter)
    const int lq    = lane >> 2;       // 0..7
    const int lr4   = lane & 3;        // 0..3

    // loader mapping: one row, 8 contiguous k per thread (BK=16)
    const int lr = tid >> 1;
    const int lc = (tid & 1) * 8;

    for (int i = tid; i < K_DIM; i += 256) csq_s[i] = g_csq[t * K_DIM + i];
    if (tid < BM) minpack[tid] = 0xFFFFFFFFFFFFFFFFull;
    __syncthreads();

    const size_t ARowStride = (size_t)T_DIM * D_DIM;
    const float* Abase = input    + ((size_t)mBase * T_DIM + t) * D_DIM;
    const float* Cb    = codebook + (size_t)t * K_DIM * D_DIM;

    float rmin[8];
    int   ridx[8];
    #pragma unroll
    for (int i = 0; i < 8; i++) { rmin[i] = 3.4e38f; ridx[i] = 0; }

    int buf = 0;
    for (int nTile = 0; nTile < K_DIM / BN; nTile++) {
        const int nBase = nTile * BN;

        float acc[4][4][4];
        #pragma unroll
        for (int mf = 0; mf < 4; mf++)
            #pragma unroll
            for (int nf = 0; nf < 4; nf++)
                #pragma unroll
                for (int r = 0; r < 4; r++) acc[mf][nf][r] = 0.0f;

        const float* Ap = Abase + (size_t)lr * ARowStride + lc;
        const float* Bp = Cb + (size_t)(nBase + lr) * D_DIM + lc;

        float va[8], vb[8];
        #pragma unroll
        for (int i = 0; i < 2; i++) {
            *reinterpret_cast<float4*>(va + i * 4) =
                *reinterpret_cast<const float4*>(Ap + i * 4);
            *reinterpret_cast<float4*>(vb + i * 4) =
                *reinterpret_cast<const float4*>(Bp + i * 4);
        }
        {
            float* Ah = bufs + buf * 4 * ARR_STRIDE;
            float* Al = Ah + ARR_STRIDE;
            float* Bh = Al + ARR_STRIDE;
            float* Bl = Bh + ARR_STRIDE;
            #pragma unroll
            for (int e = 0; e < 8; e++) {
                const int ad = KADDR(lc + e, lr);
                float ha = __uint_as_float(__float_as_uint(va[e]) & 0xFFFFE000u);
                float hb = __uint_as_float(__float_as_uint(vb[e]) & 0xFFFFE000u);
                Ah[ad] = ha; Al[ad] = va[e] - ha;
                Bh[ad] = hb; Bl[ad] = vb[e] - hb;
            }
        }
        __syncthreads();

        for (int kt = 0; kt < D_DIM / BK; kt++) {
            const bool more = (kt + 1) < (D_DIM / BK);
            if (more) {
                Ap += BK; Bp += BK;
                #pragma unroll
                for (int i = 0; i < 2; i++) {
                    *reinterpret_cast<float4*>(va + i * 4) =
                        *reinterpret_cast<const float4*>(Ap + i * 4);
                    *reinterpret_cast<float4*>(vb + i * 4) =
                        *reinterpret_cast<const float4*>(Bp + i * 4);
                }
            }

            const float* Ah = bufs + buf * 4 * ARR_STRIDE;
            const float* Al = Ah + ARR_STRIDE;
            const float* Bh = Al + ARR_STRIDE;
            const float* Bl = Bh + ARR_STRIDE;

            #pragma unroll
            for (int kf = 0; kf < 2; kf++) {
                uint32_t bh[4][2], bl[4][2];
                #pragma unroll
                for (int nf = 0; nf < 4; nf++)
                    #pragma unroll
                    for (int j = 0; j < 2; j++) {
                        const int ad = KADDR(kf * 8 + lr4 + j * 4,
                                             wn * 32 + nf * 8 + lq);
                        bh[nf][j] = __float_as_uint(Bh[ad]);
                        bl[nf][j] = __float_as_uint(Bl[ad]);
                    }
                #pragma unroll
                for (int mf = 0; mf < 4; mf++) {
                    uint32_t ah[4], al[4];
                    #pragma unroll
                    for (int j = 0; j < 4; j++) {
                        const int ad = KADDR(kf * 8 + lr4 + (j >> 1) * 4,
                                             wm * 64 + mf * 16 + lq + (j & 1) * 8);
                        ah[j] = __float_as_uint(Ah[ad]);
                        al[j] = __float_as_uint(Al[ad]);
                    }
                    #pragma unroll
                    for (int nf = 0; nf < 4; nf++) {
                        mma_tf32(acc[mf][nf], al, bh[nf]);  // small terms first
                        mma_tf32(acc[mf][nf], ah, bl[nf]);
                        mma_tf32(acc[mf][nf], ah, bh[nf]);
                    }
                }
            }

            if (more) {
                const int nb = buf ^ 1;
                float* Ahn = bufs + nb * 4 * ARR_STRIDE;
                float* Aln = Ahn + ARR_STRIDE;
                float* Bhn = Aln + ARR_STRIDE;
                float* Bln = Bhn + ARR_STRIDE;
                #pragma unroll
                for (int e = 0; e < 8; e++) {
                    const int ad = KADDR(lc + e, lr);
                    float ha = __uint_as_float(__float_as_uint(va[e]) & 0xFFFFE000u);
                    float hb = __uint_as_float(__float_as_uint(vb[e]) & 0xFFFFE000u);
                    Ahn[ad] = ha; Aln[ad] = va[e] - ha;
                    Bhn[ad] = hb; Bln[ad] = vb[e] - hb;
                }
                buf = nb;
            }
            __syncthreads();
        }

        // fold into running argmin (per-thread n strictly ascending ->
        // '<' keeps first occurrence, matching jnp.argmin)
        #pragma unroll
        for (int mf = 0; mf < 4; mf++)
            #pragma unroll
            for (int half = 0; half < 2; half++) {
                const int i = mf * 2 + half;
                #pragma unroll
                for (int nf = 0; nf < 4; nf++) {
                    const int n0 = nBase + wn * 32 + nf * 8 + lr4 * 2;
                    const float d0 = fmaf(-2.0f, acc[mf][nf][half * 2 + 0], csq_s[n0]);
                    const float d1 = fmaf(-2.0f, acc[mf][nf][half * 2 + 1], csq_s[n0 + 1]);
                    if (d0 < rmin[i]) { rmin[i] = d0; ridx[i] = n0; }
                    if (d1 < rmin[i]) { rmin[i] = d1; ridx[i] = n0 + 1; }
                }
            }
    }

    // reduce across the 4 lanes sharing each row (xor 1,2 within quad),
    // then global combine across the 4 n-warps via packed atomicMin.
    #pragma unroll
    for (int i = 0; i < 8; i++) {
        float d  = rmin[i];
        int   ix = ridx[i];
        #pragma unroll
        for (int o = 1; o <= 2; o <<= 1) {
            float od = __shfl_xor_sync(0xffffffffu, d, o);
            int   oi = __shfl_xor_sync(0xffffffffu, ix, o);
            if (od < d || (od == d && oi < ix)) { d = od; ix = oi; }
        }
        if (lr4 == 0) {
            const int row = wm * 64 + (i >> 1) * 16 + (i & 1) * 8 + lq;
            uint32_t db = __float_as_uint(d);
            uint32_t key = (db & 0x80000000u) ? ~db : (db | 0x80000000u);
            unsigned long long pk =
                ((unsigned long long)key << 32) | (uint32_t)ix;
            atomicMin(&minpack[row], pk);
        }
    }
    __syncthreads();

    // cooperative gather: embed[b,t,:] = codebook[t, argmin, :]
    for (int q = tid; q < BM * (D_DIM / 4); q += 256) {
        const int r  = q >> 6;
        const int c  = q & 63;
        const int bi = (int)(uint32_t)(minpack[r] & 0xFFFFFFFFull);
        float4 v = *reinterpret_cast<const float4*>(Cb + (size_t)bi * D_DIM + c * 4);
        *reinterpret_cast<float4*>(
            out + ((size_t)(mBase + r) * T_DIM + t) * D_DIM + c * 4) = v;
    }
    // idxes (float, concatenated after embed in the float32 output)
    if (tid < BM) {
        out[(size_t)B_DIM * T_DIM * D_DIM + (size_t)(mBase + tid) * T_DIM + t]
            = (float)(uint32_t)(minpack[tid] & 0xFFFFFFFFull);
    }
}

// ---------------------------------------------------------------------------
static const uint32_t SMEM_BYTES = (1280u + 2u * 4u * ARR_STRIDE) * 4u;  // 75264

extern "C" void kernel_launch(void* const* d_in, const int* in_sizes, int n_in,
                              void* d_out, int out_size) {
    const float* input    = (const float*)d_in[0];
    const float* codebook = (const float*)d_in[1];
    float* out = (float*)d_out;

    cudaFuncSetAttribute(vsq_mma_kernel,
                         cudaFuncAttributeMaxDynamicSharedMemorySize, SMEM_BYTES);

    csq_kernel<<<(T_DIM * K_DIM) / 8, 256>>>(codebook);

    dim3 grid(B_DIM / BM, T_DIM);
    vsq_mma_kernel<<<grid, 256, SMEM_BYTES>>>(input, codebook, out);
}